// round 2
// baseline (speedup 1.0000x reference)
#include <cuda_runtime.h>
#include <cmath>

typedef unsigned long long ull;

// Problem constants
constexpr int cB  = 32;
constexpr int cF  = 40;
constexpr int cNB = 36;
constexpr int cH  = 512;
constexpr int cD  = 1536;          // R + 2H
constexpr int cBF = cB * cF;       // 1280
constexpr int cMA = cBF * cNB;     // 46080 rows of GEMM-A

// Scratch (device globals; no allocation allowed)
__device__ float g_cs[cB * cH];          // hidden@Ws_h.T + bs_h + bs_f
__device__ float g_cr[cB * cH];          // hidden@Wr_h.T + br_h + br_f
__device__ float g_epart[4 * cMA];       // per-n-tile partial e (deterministic, no atomics)
__device__ float g_feat[cBF * cD];       // [obj_att | i3d]
__device__ float g_p12[cBF * 1024];      // [p1 | p2] per row
__device__ float g_e2[cB * cF * cF];     // stage-2 logits

// ---- packed f32x2 helpers (FFMA2: 2x fp32 FLOP per issue slot) ----
__device__ __forceinline__ ull pack2(float x, float y) {
    ull v; asm("mov.b64 %0, {%1, %2};" : "=l"(v) : "f"(x), "f"(y)); return v;
}
__device__ __forceinline__ float2 unpack2(ull v) {
    float2 f; asm("mov.b64 {%0, %1}, %2;" : "=f"(f.x), "=f"(f.y) : "l"(v)); return f;
}
__device__ __forceinline__ ull ffma2(ull a, ull b, ull c) {
    ull d; asm("fma.rn.f32x2 %0, %1, %2, %3;" : "=l"(d) : "l"(a), "l"(b), "l"(c)); return d;
}

// ============================================================
// Kernel 1: combined hidden-state biases c_s, c_r (32 x 512 each)
// ============================================================
__global__ void k_bias(const float* __restrict__ hidden,
                       const float* __restrict__ Wsh, const float* __restrict__ bsh,
                       const float* __restrict__ bsf,
                       const float* __restrict__ Wrh, const float* __restrict__ brh,
                       const float* __restrict__ brf) {
    int b = blockIdx.x;
    __shared__ __align__(16) float sh[cH];
    for (int i = threadIdx.x; i < cH; i += blockDim.x) sh[i] = hidden[b * cH + i];
    __syncthreads();
    for (int h = threadIdx.x; h < cH; h += blockDim.x) {
        const float4* w1 = (const float4*)(Wsh + (size_t)h * cH);
        const float4* w2 = (const float4*)(Wrh + (size_t)h * cH);
        const float4* s4 = (const float4*)sh;
        float a1 = 0.f, a2 = 0.f;
        #pragma unroll 8
        for (int k = 0; k < cH / 4; k++) {
            float4 s = s4[k];
            float4 v = w1[k];
            a1 += v.x * s.x + v.y * s.y + v.z * s.z + v.w * s.w;
            float4 u = w2[k];
            a2 += u.x * s.x + u.y * s.y + u.z * s.z + u.w * s.w;
        }
        g_cs[b * cH + h] = a1 + bsh[h] + bsf[h];
        g_cr[b * cH + h] = a2 + brh[h] + brf[h];
    }
}

// ============================================================
// GEMM: C = A(MxK, row-major) * W^T, 128x128 CTA tile, 8x8/thread, FFMA2.
// MODE 1: A=object_feats (param), W=Ws_f (N=512). Fused epilogue:
//         e_partial[m] += sum_n tanh(y + c_s[b,n]) * was[n]  (per n-tile)
// MODE 0: A=g_feat (K=1536), W=Wr_f remapped rows (N=1024 -> p1|p2),
//         writes g_p12 directly.
// ============================================================
template <int MODE>
__global__ void __launch_bounds__(256, 2)
k_gemm(const float* __restrict__ Ap, const float* __restrict__ W,
       const float* __restrict__ was, int K) {
    const float* A = (MODE == 1) ? Ap : (const float*)g_feat;
    const int m0 = blockIdx.x * 128;
    const int n0 = blockIdx.y * 128;
    __shared__ __align__(16) float As[2][16][132];
    __shared__ __align__(16) float Bs[2][16][132];

    const int tid = threadIdx.x;
    const int tx  = tid & 15;     // n sub-tile
    const int ty  = tid >> 4;     // m sub-tile
    const int lr  = tid >> 1;     // 0..127: tile row loaded by this thread
    const int lc  = (tid & 1) * 2;// float4 col pair 0 or 2
    const int c0  = lc * 4;

    const float* aptr = A + (size_t)(m0 + lr) * K + c0;
    const float* bptr;
    if (MODE == 0) {
        int n = n0 + lr;
        bptr = (n < 512) ? (W + (size_t)n * 3072 + c0)
                         : (W + (size_t)(n - 512) * 3072 + 1536 + c0);
    } else {
        bptr = W + (size_t)(n0 + lr) * 512 + c0;
    }

    // stage 0 load
    float4 pa0 = *(const float4*)(aptr);
    float4 pa1 = *(const float4*)(aptr + 4);
    float4 pb0 = *(const float4*)(bptr);
    float4 pb1 = *(const float4*)(bptr + 4);
    As[0][c0 + 0][lr] = pa0.x; As[0][c0 + 1][lr] = pa0.y;
    As[0][c0 + 2][lr] = pa0.z; As[0][c0 + 3][lr] = pa0.w;
    As[0][c0 + 4][lr] = pa1.x; As[0][c0 + 5][lr] = pa1.y;
    As[0][c0 + 6][lr] = pa1.z; As[0][c0 + 7][lr] = pa1.w;
    Bs[0][c0 + 0][lr] = pb0.x; Bs[0][c0 + 1][lr] = pb0.y;
    Bs[0][c0 + 2][lr] = pb0.z; Bs[0][c0 + 3][lr] = pb0.w;
    Bs[0][c0 + 4][lr] = pb1.x; Bs[0][c0 + 5][lr] = pb1.y;
    Bs[0][c0 + 6][lr] = pb1.z; Bs[0][c0 + 7][lr] = pb1.w;
    __syncthreads();

    ull acc[8][4];
    #pragma unroll
    for (int i = 0; i < 8; i++)
        #pragma unroll
        for (int j = 0; j < 4; j++) acc[i][j] = 0ull;

    const int nst = K >> 4;
    int buf = 0;
    for (int s = 0; s < nst; s++) {
        const int ks = (s + 1) << 4;
        const bool more = (s + 1 < nst);
        if (more) {
            pa0 = *(const float4*)(aptr + ks);
            pa1 = *(const float4*)(aptr + ks + 4);
            pb0 = *(const float4*)(bptr + ks);
            pb1 = *(const float4*)(bptr + ks + 4);
        }
        #pragma unroll
        for (int kk = 0; kk < 16; kk++) {
            float4 a0 = *(const float4*)&As[buf][kk][ty * 8];
            float4 a1 = *(const float4*)&As[buf][kk][ty * 8 + 4];
            float4 b0 = *(const float4*)&Bs[buf][kk][tx * 8];
            float4 b1 = *(const float4*)&Bs[buf][kk][tx * 8 + 4];
            ull bb0 = pack2(b0.x, b0.y), bb1 = pack2(b0.z, b0.w);
            ull bb2 = pack2(b1.x, b1.y), bb3 = pack2(b1.z, b1.w);
            float av[8] = {a0.x, a0.y, a0.z, a0.w, a1.x, a1.y, a1.z, a1.w};
            #pragma unroll
            for (int i = 0; i < 8; i++) {
                ull ad = pack2(av[i], av[i]);
                acc[i][0] = ffma2(ad, bb0, acc[i][0]);
                acc[i][1] = ffma2(ad, bb1, acc[i][1]);
                acc[i][2] = ffma2(ad, bb2, acc[i][2]);
                acc[i][3] = ffma2(ad, bb3, acc[i][3]);
            }
        }
        if (more) {
            int nb = buf ^ 1;
            As[nb][c0 + 0][lr] = pa0.x; As[nb][c0 + 1][lr] = pa0.y;
            As[nb][c0 + 2][lr] = pa0.z; As[nb][c0 + 3][lr] = pa0.w;
            As[nb][c0 + 4][lr] = pa1.x; As[nb][c0 + 5][lr] = pa1.y;
            As[nb][c0 + 6][lr] = pa1.z; As[nb][c0 + 7][lr] = pa1.w;
            Bs[nb][c0 + 0][lr] = pb0.x; Bs[nb][c0 + 1][lr] = pb0.y;
            Bs[nb][c0 + 2][lr] = pb0.z; Bs[nb][c0 + 3][lr] = pb0.w;
            Bs[nb][c0 + 4][lr] = pb1.x; Bs[nb][c0 + 5][lr] = pb1.y;
            Bs[nb][c0 + 6][lr] = pb1.z; Bs[nb][c0 + 7][lr] = pb1.w;
            __syncthreads();
            buf = nb;
        }
    }

    if constexpr (MODE == 1) {
        // fused tanh/was reduction over this CTA's 128 n-columns
        __shared__ float red[16][16][8];   // [ty][tx][i]
        float wv[8];
        #pragma unroll
        for (int j = 0; j < 8; j++) wv[j] = was[n0 + tx * 8 + j];
        #pragma unroll
        for (int i = 0; i < 8; i++) {
            int m = m0 + ty * 8 + i;
            int b = m / (cF * cNB);
            const float* cs = g_cs + b * cH + n0 + tx * 8;
            float p = 0.f;
            #pragma unroll
            for (int j2 = 0; j2 < 4; j2++) {
                float2 v = unpack2(acc[i][j2]);
                p += tanhf(v.x + cs[2 * j2])     * wv[2 * j2];
                p += tanhf(v.y + cs[2 * j2 + 1]) * wv[2 * j2 + 1];
            }
            red[ty][tx][i] = p;
        }
        __syncthreads();
        if (tid < 128) {
            int ry = tid >> 3, i = tid & 7;
            float ssum = 0.f;
            #pragma unroll
            for (int t = 0; t < 16; t++) ssum += red[ry][t][i];
            g_epart[(size_t)blockIdx.y * cMA + m0 + ry * 8 + i] = ssum;
        }
    } else {
        #pragma unroll
        for (int i = 0; i < 8; i++) {
            int m = m0 + ty * 8 + i;
            float2 v0 = unpack2(acc[i][0]), v1 = unpack2(acc[i][1]);
            float2 v2 = unpack2(acc[i][2]), v3 = unpack2(acc[i][3]);
            float4 o0 = make_float4(v0.x, v0.y, v1.x, v1.y);
            float4 o1 = make_float4(v2.x, v2.y, v3.x, v3.y);
            *(float4*)&g_p12[(size_t)m * 1024 + n0 + tx * 8]     = o0;
            *(float4*)&g_p12[(size_t)m * 1024 + n0 + tx * 8 + 4] = o1;
        }
    }
}

// ============================================================
// Kernel: softmax over NB, object attention, and feat assembly
// grid = 1280 (one per (b,f)); feat = [att(512) | i3d(1024)]
// ============================================================
__global__ void k_objatt(const float* __restrict__ obj, const float* __restrict__ i3d) {
    int bf = blockIdx.x;
    __shared__ float sa[cNB];
    int tid = threadIdx.x;
    if (tid < cNB) {
        int idx = bf * cNB + tid;
        sa[tid] = g_epart[idx] + g_epart[cMA + idx] +
                  g_epart[2 * cMA + idx] + g_epart[3 * cMA + idx];
    }
    __syncthreads();
    float mx = -1e30f;
    #pragma unroll
    for (int j = 0; j < cNB; j++) mx = fmaxf(mx, sa[j]);
    float ssum = 0.f;
    #pragma unroll
    for (int j = 0; j < cNB; j++) ssum += expf(sa[j] - mx);
    float inv = 1.f / ssum;
    __syncthreads();
    if (tid < cNB) sa[tid] = expf(sa[tid] - mx) * inv;
    __syncthreads();

    const float* f0 = obj + (size_t)bf * cNB * 512;
    float* fo = g_feat + (size_t)bf * cD;
    for (int d = tid; d < 512; d += blockDim.x) {
        float acc = 0.f;
        #pragma unroll
        for (int j = 0; j < cNB; j++) acc += sa[j] * f0[j * 512 + d];
        fo[d] = acc;
    }
    const float* i0 = i3d + (size_t)bf * 1024;
    for (int d = tid; d < 1024; d += blockDim.x) fo[512 + d] = i0[d];
}

// ============================================================
// Kernel: stage-2 logits e2[b,i,j] = sum_h tanh(p2[b,i,h]+p1[b,j,h]+c_r[b,h])*war[h]
// grid = (40, 32): one CTA per (i, b); warp per j.
// ============================================================
__global__ void k_e2(const float* __restrict__ war) {
    int i = blockIdx.x, b = blockIdx.y;
    __shared__ float s2[cH];
    __shared__ float swar[cH];
    int tid = threadIdx.x;
    for (int h = tid; h < cH; h += blockDim.x) {
        s2[h]   = g_p12[(size_t)(b * cF + i) * 1024 + 512 + h] + g_cr[b * cH + h];
        swar[h] = war[h];
    }
    __syncthreads();
    int w = tid >> 5, lane = tid & 31;
    for (int j = w; j < cF; j += 8) {
        const float* p1 = g_p12 + (size_t)(b * cF + j) * 1024;
        float acc = 0.f;
        #pragma unroll 4
        for (int h = lane; h < cH; h += 32)
            acc += tanhf(p1[h] + s2[h]) * swar[h];
        #pragma unroll
        for (int o = 16; o; o >>= 1) acc += __shfl_xor_sync(0xffffffffu, acc, o);
        if (lane == 0) g_e2[b * 1600 + i * cF + j] = acc;
    }
}

// ============================================================
// Kernel: softmax over 1600, row/col sums, rel1/rel2, final output
// ============================================================
__global__ void k_rel(float* __restrict__ out) {
    int b = blockIdx.x;
    __shared__ float sa[1600];
    __shared__ float ssr[cF], ssc[cF];
    __shared__ float rbuf[256];
    int tid = threadIdx.x;

    float mx = -1e30f;
    for (int t = tid; t < 1600; t += 256) {
        float v = g_e2[b * 1600 + t];
        sa[t] = v;
        mx = fmaxf(mx, v);
    }
    rbuf[tid] = mx; __syncthreads();
    for (int s = 128; s; s >>= 1) {
        if (tid < s) rbuf[tid] = fmaxf(rbuf[tid], rbuf[tid + s]);
        __syncthreads();
    }
    mx = rbuf[0]; __syncthreads();

    float sum = 0.f;
    for (int t = tid; t < 1600; t += 256) {
        float v = expf(sa[t] - mx);
        sa[t] = v;
        sum += v;
    }
    rbuf[tid] = sum; __syncthreads();
    for (int s = 128; s; s >>= 1) {
        if (tid < s) rbuf[tid] += rbuf[tid + s];
        __syncthreads();
    }
    float inv = 1.f / rbuf[0];
    __syncthreads();

    if (tid < cF) {
        float rs = 0.f, cs2 = 0.f;
        for (int t = 0; t < cF; t++) {
            rs  += sa[tid * cF + t];   // row sum i (for rel2)
            cs2 += sa[t * cF + tid];   // col sum j (for rel1)
        }
        ssr[tid] = rs * inv;
        ssc[tid] = cs2 * inv;
    }
    __syncthreads();

    const float* fb = g_feat + (size_t)b * cF * cD;
    for (int d = tid; d < cD; d += 256) {
        float r1 = 0.f, r2 = 0.f;
        #pragma unroll 8
        for (int t = 0; t < cF; t++) {
            float f = fb[(size_t)t * cD + d];
            r1 += ssc[t] * f;
            r2 += ssr[t] * f;
        }
        out[b * 3072 + d]        = r1;
        out[b * 3072 + 1536 + d] = r2;
    }
}

// ============================================================
extern "C" void kernel_launch(void* const* d_in, const int* in_sizes, int n_in,
                              void* d_out, int out_size) {
    const float* i3d    = (const float*)d_in[0];
    const float* obj    = (const float*)d_in[1];
    const float* hidden = (const float*)d_in[2];
    const float* Wsf    = (const float*)d_in[3];
    const float* bsf    = (const float*)d_in[4];
    const float* Wsh    = (const float*)d_in[5];
    const float* bsh    = (const float*)d_in[6];
    const float* was    = (const float*)d_in[7];
    const float* Wrf    = (const float*)d_in[8];
    const float* brf    = (const float*)d_in[9];
    const float* Wrh    = (const float*)d_in[10];
    const float* brh    = (const float*)d_in[11];
    const float* war    = (const float*)d_in[12];
    float* out = (float*)d_out;

    // 1. biases
    k_bias<<<cB, 256>>>(hidden, Wsh, bsh, bsf, Wrh, brh, brf);
    // 2. GEMM-A with fused tanh/was row-reduce (partials per n-tile)
    k_gemm<1><<<dim3(cMA / 128, 4), 256>>>(obj, Wsf, was, 512);
    // 3. softmax-36 + object attention + feat assembly
    k_objatt<<<cBF, 256>>>(obj, i3d);
    // 4. p1/p2 GEMM -> g_p12
    k_gemm<0><<<dim3(cBF / 128, 8), 256>>>(nullptr, Wrf, nullptr, 1536);
    // 5. stage-2 logits
    k_e2<<<dim3(cF, cB), 256>>>(war);
    // 6. softmax-1600 + rel1/rel2 + output
    k_rel<<<cB, 256>>>(out);
}

// round 12
// speedup vs baseline: 1.5601x; 1.5601x over previous
#include <cuda_runtime.h>
#include <cuda_bf16.h>
#include <cmath>
#include <cstdint>

typedef unsigned long long ull;

// Problem constants
constexpr int cB  = 32;
constexpr int cF  = 40;
constexpr int cNB = 36;
constexpr int cH  = 512;
constexpr int cD  = 1536;          // R + 2H
constexpr int cBF = cB * cF;       // 1280
constexpr int cMA = cBF * cNB;     // 46080 rows of GEMM-A

// Scratch (device globals; no allocation allowed)
__device__ float g_cs[cB * cH];
__device__ float g_cr[cB * cH];
__device__ float g_epart[4 * cMA];               // per-n-tile partial e
__device__ float g_feat[cBF * cD];               // [obj_att | i3d] fp32
__device__ float g_p12[cBF * 1024];              // [p1 | p2]
__device__ float g_p12p[2 * cBF * 1024];         // split-K partials
__device__ float g_e2[cB * cF * cF];
__device__ __nv_bfloat16 g_whi[cH * cH];         // Ws_f hi
__device__ __nv_bfloat16 g_wlo[cH * cH];         // Ws_f lo
__device__ __nv_bfloat16 g_wrhi[1024 * cD];      // Wr remapped hi
__device__ __nv_bfloat16 g_wrlo[1024 * cD];      // Wr remapped lo
__device__ __nv_bfloat16 g_ahi[cMA * cH];        // obj hi
__device__ __nv_bfloat16 g_alo[cMA * cH];        // obj lo
__device__ __nv_bfloat16 g_fhi[cBF * cD];        // feat hi
__device__ __nv_bfloat16 g_flo[cBF * cD];        // feat lo

// ---------------- PTX helpers (all family-target-safe, sm_80+) ----------------
__device__ __forceinline__ uint32_t smem_u32(const void* p) {
    uint32_t a;
    asm("{ .reg .u64 t; cvta.to.shared.u64 t, %1; cvt.u32.u64 %0, t; }"
        : "=r"(a) : "l"(p));
    return a;
}
#define CPA(dst, src) \
    asm volatile("cp.async.cg.shared.global [%0], [%1], 16;" :: "r"(dst), "l"(src) : "memory")
#define CPC()  asm volatile("cp.async.commit_group;" ::: "memory")
#define CPW1() asm volatile("cp.async.wait_group 1;" ::: "memory")
#define CPW0() asm volatile("cp.async.wait_group 0;" ::: "memory")
#define LDSM4(r0, r1, r2, r3, addr) \
    asm volatile("ldmatrix.sync.aligned.m8n8.x4.shared.b16 {%0,%1,%2,%3}, [%4];" \
        : "=r"(r0), "=r"(r1), "=r"(r2), "=r"(r3) : "r"(addr))
#define MMA(c, a, b0, b1) \
    asm volatile("mma.sync.aligned.m16n8k16.row.col.f32.bf16.bf16.f32 " \
        "{%0,%1,%2,%3},{%4,%5,%6,%7},{%8,%9},{%0,%1,%2,%3};" \
        : "+f"((c)[0]), "+f"((c)[1]), "+f"((c)[2]), "+f"((c)[3]) \
        : "r"((a)[0]), "r"((a)[1]), "r"((a)[2]), "r"((a)[3]), "r"(b0), "r"(b1))

__device__ __forceinline__ void split1(float x, __nv_bfloat16& h, __nv_bfloat16& l) {
    h = __float2bfloat16_rn(x);
    l = __float2bfloat16_rn(x - __bfloat162float(h));
}

// ============================================================
// Pre-splits
// ============================================================
__global__ void k_wsplit(const float* __restrict__ w) {
    int i = blockIdx.x * 256 + threadIdx.x;          // 262144
    __nv_bfloat16 h, l; split1(w[i], h, l);
    g_whi[i] = h; g_wlo[i] = l;
}
__global__ void k_wrsplit(const float* __restrict__ w) {
    int n = blockIdx.x;                              // 1024
    for (int k = threadIdx.x; k < cD; k += 256) {
        float x = (n < 512) ? w[(size_t)n * 3072 + k]
                            : w[(size_t)(n - 512) * 3072 + 1536 + k];
        __nv_bfloat16 h, l; split1(x, h, l);
        g_wrhi[(size_t)n * cD + k] = h; g_wrlo[(size_t)n * cD + k] = l;
    }
}
__global__ void k_asplit(const float* __restrict__ a) {
    size_t i4 = (size_t)blockIdx.x * 256 + threadIdx.x;   // grid 23040 -> 5.9M float4
    float4 v = ((const float4*)a)[i4];
    __nv_bfloat16 h0, h1, h2, h3, l0, l1, l2, l3;
    split1(v.x, h0, l0); split1(v.y, h1, l1);
    split1(v.z, h2, l2); split1(v.w, h3, l3);
    ull hp = (ull)__bfloat16_as_ushort(h0) | ((ull)__bfloat16_as_ushort(h1) << 16)
           | ((ull)__bfloat16_as_ushort(h2) << 32) | ((ull)__bfloat16_as_ushort(h3) << 48);
    ull lp = (ull)__bfloat16_as_ushort(l0) | ((ull)__bfloat16_as_ushort(l1) << 16)
           | ((ull)__bfloat16_as_ushort(l2) << 32) | ((ull)__bfloat16_as_ushort(l3) << 48);
    ((ull*)g_ahi)[i4] = hp;
    ((ull*)g_alo)[i4] = lp;
}

// ============================================================
// Combined hidden-state biases c_s, c_r
// ============================================================
__global__ void k_bias(const float* __restrict__ hidden,
                       const float* __restrict__ Wsh, const float* __restrict__ bsh,
                       const float* __restrict__ bsf,
                       const float* __restrict__ Wrh, const float* __restrict__ brh,
                       const float* __restrict__ brf) {
    int b = blockIdx.x;
    __shared__ __align__(16) float sh[cH];
    for (int i = threadIdx.x; i < cH; i += blockDim.x) sh[i] = hidden[b * cH + i];
    __syncthreads();
    for (int h = threadIdx.x; h < cH; h += blockDim.x) {
        const float4* w1 = (const float4*)(Wsh + (size_t)h * cH);
        const float4* w2 = (const float4*)(Wrh + (size_t)h * cH);
        const float4* s4 = (const float4*)sh;
        float a1 = 0.f, a2 = 0.f;
        #pragma unroll 8
        for (int k = 0; k < cH / 4; k++) {
            float4 s = s4[k];
            float4 v = w1[k];
            a1 += v.x * s.x + v.y * s.y + v.z * s.z + v.w * s.w;
            float4 u = w2[k];
            a2 += u.x * s.x + u.y * s.y + u.z * s.z + u.w * s.w;
        }
        g_cs[b * cH + h] = a1 + bsh[h] + bsf[h];
        g_cr[b * cH + h] = a2 + brh[h] + brf[h];
    }
}

// ============================================================
// Tensor-core GEMM via mma.sync bf16 (2-term split: hh + hl + lh)
// CTA tile 128x128, K-chunk 32, cp.async double buffer.
// 8 warps = 4(m) x 2(n); warp tile 32x64.
// MODE 1: A=g_ahi/alo (K=512), W=g_whi/wlo; epilogue tanh*was reduce
//         -> g_epart[blockIdx.y] slice. grid (360,4).
// MODE 0: A=g_fhi/flo (K=1536), W=g_wrhi/wrlo; split-K via blockIdx.z
//         -> g_p12p slice. grid (10,8,2).
// ============================================================
constexpr int SMEM_TC = 81920;   // 2 stages x 4 matrices x 128 rows x 40 b16

template <int MODE>
__global__ void __launch_bounds__(256, 1) k_tc(const float* __restrict__ was) {
    constexpr int K   = MODE ? cH : cD;
    constexpr int NCH = MODE ? 16 : 24;
    const __nv_bfloat16* Ah = MODE ? g_ahi : g_fhi;
    const __nv_bfloat16* Al = MODE ? g_alo : g_flo;
    const __nv_bfloat16* Wh = MODE ? g_whi : g_wrhi;
    const __nv_bfloat16* Wl = MODE ? g_wlo : g_wrlo;

    const int m0 = blockIdx.x * 128;
    const int n0 = blockIdx.y * 128;
    const int kstart = MODE ? 0 : blockIdx.z * 768;

    extern __shared__ char sm[];
    const uint32_t S = smem_u32(sm);
    const int tid = threadIdx.x;
    const int wid = tid >> 5, l = tid & 31;
    const int wm = wid >> 1, wn = wid & 1;

    auto issue = [&](int c) {
        const int st = c & 1;
        const int kb = kstart + c * 32;
        const int row = tid >> 1, h = tid & 1;
        const uint32_t d0 = S + st * 40960 + row * 80 + h * 32;
        const __nv_bfloat16* s1 = Ah + (size_t)(m0 + row) * K + kb + 16 * h;
        CPA(d0, s1);           CPA(d0 + 16, s1 + 8);
        const __nv_bfloat16* s2 = Al + (size_t)(m0 + row) * K + kb + 16 * h;
        CPA(d0 + 10240, s2);   CPA(d0 + 10240 + 16, s2 + 8);
        const __nv_bfloat16* s3 = Wh + (size_t)(n0 + row) * K + kb + 16 * h;
        CPA(d0 + 20480, s3);   CPA(d0 + 20480 + 16, s3 + 8);
        const __nv_bfloat16* s4 = Wl + (size_t)(n0 + row) * K + kb + 16 * h;
        CPA(d0 + 30720, s4);   CPA(d0 + 30720 + 16, s4 + 8);
        CPC();
    };

    float acc[2][8][4];
    #pragma unroll
    for (int i = 0; i < 2; i++)
        #pragma unroll
        for (int j = 0; j < 8; j++)
            #pragma unroll
            for (int q = 0; q < 4; q++) acc[i][j][q] = 0.f;

    issue(0); issue(1);

    for (int c = 0; c < NCH; ++c) {
        if (c + 1 < NCH) { CPW1(); } else { CPW0(); }
        __syncthreads();
        const int st = c & 1;
        #pragma unroll
        for (int kb16 = 0; kb16 < 64; kb16 += 32) {     // byte offset of k16 step
            uint32_t aH[2][4], aL[2][4];
            const uint32_t abase = S + st * 40960 + (32 * wm + (l & 15)) * 80
                                 + kb16 + ((l >> 4) << 4);
            LDSM4(aH[0][0], aH[0][1], aH[0][2], aH[0][3], abase);
            LDSM4(aH[1][0], aH[1][1], aH[1][2], aH[1][3], abase + 1280);
            LDSM4(aL[0][0], aL[0][1], aL[0][2], aL[0][3], abase + 10240);
            LDSM4(aL[1][0], aL[1][1], aL[1][2], aL[1][3], abase + 10240 + 1280);
            uint32_t bH[8][2], bL[8][2];
            #pragma unroll
            for (int ntp = 0; ntp < 4; ++ntp) {
                const uint32_t bb = S + st * 40960 + 20480
                    + (64 * wn + 16 * ntp + (l & 7) + ((l >> 4) << 3)) * 80
                    + kb16 + (((l >> 3) & 1) << 4);
                LDSM4(bH[2 * ntp][0], bH[2 * ntp][1], bH[2 * ntp + 1][0], bH[2 * ntp + 1][1], bb);
                LDSM4(bL[2 * ntp][0], bL[2 * ntp][1], bL[2 * ntp + 1][0], bL[2 * ntp + 1][1], bb + 10240);
            }
            #pragma unroll
            for (int mt = 0; mt < 2; ++mt)
                #pragma unroll
                for (int nt = 0; nt < 8; ++nt) {
                    MMA(acc[mt][nt], aH[mt], bH[nt][0], bH[nt][1]);
                    MMA(acc[mt][nt], aH[mt], bL[nt][0], bL[nt][1]);
                    MMA(acc[mt][nt], aL[mt], bH[nt][0], bH[nt][1]);
                }
        }
        __syncthreads();
        if (c + 2 < NCH) issue(c + 2);
    }

    if constexpr (MODE == 1) {
        // fused tanh(y + cs)*was reduction over this CTA's 128 n-cols
        float* sred = (float*)sm;                     // [128][2]
        #pragma unroll
        for (int mt = 0; mt < 2; ++mt)
            #pragma unroll
            for (int rr = 0; rr < 2; ++rr) {
                const int row_l = 32 * wm + 16 * mt + (l >> 2) + 8 * rr;
                const int m = m0 + row_l;
                const int b = m / (cF * cNB);
                float p = 0.f;
                #pragma unroll
                for (int nt = 0; nt < 8; ++nt) {
                    const int n = n0 + 64 * wn + 8 * nt + 2 * (l & 3);
                    p += tanhf(acc[mt][nt][2 * rr]     + g_cs[b * cH + n])     * was[n];
                    p += tanhf(acc[mt][nt][2 * rr + 1] + g_cs[b * cH + n + 1]) * was[n + 1];
                }
                p += __shfl_xor_sync(0xffffffffu, p, 1);
                p += __shfl_xor_sync(0xffffffffu, p, 2);
                if ((l & 3) == 0) sred[row_l * 2 + wn] = p;
            }
        __syncthreads();
        if (tid < 128)
            g_epart[(size_t)blockIdx.y * cMA + m0 + tid] = sred[tid * 2] + sred[tid * 2 + 1];
    } else {
        float* outp = g_p12p + (size_t)blockIdx.z * cBF * 1024;
        #pragma unroll
        for (int mt = 0; mt < 2; ++mt)
            #pragma unroll
            for (int rr = 0; rr < 2; ++rr) {
                const int m = m0 + 32 * wm + 16 * mt + (l >> 2) + 8 * rr;
                #pragma unroll
                for (int nt = 0; nt < 8; ++nt) {
                    const int n = n0 + 64 * wn + 8 * nt + 2 * (l & 3);
                    float2 v = make_float2(acc[mt][nt][2 * rr], acc[mt][nt][2 * rr + 1]);
                    *(float2*)&outp[(size_t)m * 1024 + n] = v;
                }
            }
    }
}

// split-K partial reduce: g_p12 = sum of 2 partials
__global__ void k_p12red() {
    const float4* s = (const float4*)g_p12p;
    float4* d = (float4*)g_p12;
    size_t i = (size_t)blockIdx.x * 256 + threadIdx.x;   // grid 1280
    float4 a = s[i], b = s[i + (size_t)cBF * 256];
    d[i] = make_float4(a.x + b.x, a.y + b.y, a.z + b.z, a.w + b.w);
}

// ============================================================
// softmax-36 + object attention + feat assembly (fp32 + bf16 split)
// ============================================================
__global__ void k_objatt(const float* __restrict__ obj, const float* __restrict__ i3d) {
    int bf = blockIdx.x;
    __shared__ float sa[cNB];
    int tid = threadIdx.x;
    if (tid < cNB) {
        int idx = bf * cNB + tid;
        sa[tid] = g_epart[idx] + g_epart[cMA + idx]
                + g_epart[2 * cMA + idx] + g_epart[3 * cMA + idx];
    }
    __syncthreads();
    float mx = -1e30f;
    #pragma unroll
    for (int j = 0; j < cNB; j++) mx = fmaxf(mx, sa[j]);
    float ssum = 0.f;
    #pragma unroll
    for (int j = 0; j < cNB; j++) ssum += expf(sa[j] - mx);
    float inv = 1.f / ssum;
    __syncthreads();
    if (tid < cNB) sa[tid] = expf(sa[tid] - mx) * inv;
    __syncthreads();

    const float* f0 = obj + (size_t)bf * cNB * 512;
    float* fo = g_feat + (size_t)bf * cD;
    for (int d = tid; d < 512; d += blockDim.x) {
        float a = 0.f;
        #pragma unroll
        for (int j = 0; j < cNB; j++) a += sa[j] * f0[j * 512 + d];
        fo[d] = a;
        __nv_bfloat16 h, l; split1(a, h, l);
        g_fhi[(size_t)bf * cD + d] = h; g_flo[(size_t)bf * cD + d] = l;
    }
    const float* i0 = i3d + (size_t)bf * 1024;
    for (int d = tid; d < 1024; d += blockDim.x) {
        float a = i0[d];
        fo[512 + d] = a;
        __nv_bfloat16 h, l; split1(a, h, l);
        g_fhi[(size_t)bf * cD + 512 + d] = h; g_flo[(size_t)bf * cD + 512 + d] = l;
    }
}

// ============================================================
// stage-2 logits
// ============================================================
__global__ void k_e2(const float* __restrict__ war) {
    int i = blockIdx.x, b = blockIdx.y;
    __shared__ float s2[cH];
    __shared__ float swar[cH];
    int tid = threadIdx.x;
    for (int h = tid; h < cH; h += blockDim.x) {
        s2[h]   = g_p12[(size_t)(b * cF + i) * 1024 + 512 + h] + g_cr[b * cH + h];
        swar[h] = war[h];
    }
    __syncthreads();
    int w = tid >> 5, lane = tid & 31;
    for (int j = w; j < cF; j += 8) {
        const float* p1 = g_p12 + (size_t)(b * cF + j) * 1024;
        float a = 0.f;
        #pragma unroll 4
        for (int h = lane; h < cH; h += 32)
            a += tanhf(p1[h] + s2[h]) * swar[h];
        #pragma unroll
        for (int o = 16; o; o >>= 1) a += __shfl_xor_sync(0xffffffffu, a, o);
        if (lane == 0) g_e2[b * 1600 + i * cF + j] = a;
    }
}

// ============================================================
// softmax-1600 + rel1/rel2 + output
// ============================================================
__global__ void k_rel(float* __restrict__ out) {
    int b = blockIdx.x;
    __shared__ float sa[1600];
    __shared__ float ssr[cF], ssc[cF];
    __shared__ float rbuf[256];
    int tid = threadIdx.x;

    float mx = -1e30f;
    for (int t = tid; t < 1600; t += 256) {
        float v = g_e2[b * 1600 + t];
        sa[t] = v;
        mx = fmaxf(mx, v);
    }
    rbuf[tid] = mx; __syncthreads();
    for (int s = 128; s; s >>= 1) {
        if (tid < s) rbuf[tid] = fmaxf(rbuf[tid], rbuf[tid + s]);
        __syncthreads();
    }
    mx = rbuf[0]; __syncthreads();

    float sum = 0.f;
    for (int t = tid; t < 1600; t += 256) {
        float v = expf(sa[t] - mx);
        sa[t] = v;
        sum += v;
    }
    rbuf[tid] = sum; __syncthreads();
    for (int s = 128; s; s >>= 1) {
        if (tid < s) rbuf[tid] += rbuf[tid + s];
        __syncthreads();
    }
    float inv = 1.f / rbuf[0];
    __syncthreads();

    if (tid < cF) {
        float rs = 0.f, cs2 = 0.f;
        for (int t = 0; t < cF; t++) {
            rs  += sa[tid * cF + t];
            cs2 += sa[t * cF + tid];
        }
        ssr[tid] = rs * inv;
        ssc[tid] = cs2 * inv;
    }
    __syncthreads();

    const float* fb = g_feat + (size_t)b * cF * cD;
    for (int d = tid; d < cD; d += 256) {
        float r1 = 0.f, r2 = 0.f;
        #pragma unroll 8
        for (int t = 0; t < cF; t++) {
            float f = fb[(size_t)t * cD + d];
            r1 += ssc[t] * f;
            r2 += ssr[t] * f;
        }
        out[b * 3072 + d]        = r1;
        out[b * 3072 + 1536 + d] = r2;
    }
}

// ============================================================
extern "C" void kernel_launch(void* const* d_in, const int* in_sizes, int n_in,
                              void* d_out, int out_size) {
    const float* i3d    = (const float*)d_in[0];
    const float* obj    = (const float*)d_in[1];
    const float* hidden = (const float*)d_in[2];
    const float* Wsf    = (const float*)d_in[3];
    const float* bsf    = (const float*)d_in[4];
    const float* Wsh    = (const float*)d_in[5];
    const float* bsh    = (const float*)d_in[6];
    const float* was    = (const float*)d_in[7];
    const float* Wrf    = (const float*)d_in[8];
    const float* brf    = (const float*)d_in[9];
    const float* Wrh    = (const float*)d_in[10];
    const float* brh    = (const float*)d_in[11];
    const float* war    = (const float*)d_in[12];
    float* out = (float*)d_out;

    cudaFuncSetAttribute(k_tc<1>, cudaFuncAttributeMaxDynamicSharedMemorySize, SMEM_TC);
    cudaFuncSetAttribute(k_tc<0>, cudaFuncAttributeMaxDynamicSharedMemorySize, SMEM_TC);

    k_wsplit<<<1024, 256>>>(Wsf);
    k_wrsplit<<<1024, 256>>>(Wrf);
    k_asplit<<<23040, 256>>>(obj);
    k_bias<<<cB, 256>>>(hidden, Wsh, bsh, bsf, Wrh, brh, brf);
    k_tc<1><<<dim3(360, 4), 256, SMEM_TC>>>(was);
    k_objatt<<<cBF, 256>>>(obj, i3d);
    k_tc<0><<<dim3(10, 8, 2), 256, SMEM_TC>>>(nullptr);
    k_p12red<<<1280, 256>>>();
    k_e2<<<dim3(cF, cB), 256>>>(war);
    k_rel<<<cB, 256>>>(out);
}

// round 14
// speedup vs baseline: 1.7170x; 1.1006x over previous
#include <cuda_runtime.h>
#include <cuda_bf16.h>
#include <cmath>
#include <cstdint>

typedef unsigned long long ull;

// Problem constants
constexpr int cB  = 32;
constexpr int cF  = 40;
constexpr int cNB = 36;
constexpr int cH  = 512;
constexpr int cD  = 1536;          // R + 2H
constexpr int cBF = cB * cF;       // 1280
constexpr int cMA = cBF * cNB;     // 46080 rows of GEMM-A

// Scratch (device globals; no allocation allowed)
__device__ float g_cs[cB * cH];
__device__ float g_cr[cB * cH];
__device__ float g_epart[4 * cMA];               // per-n-tile partial e
__device__ float g_feat[cBF * cD];               // [obj_att | i3d] fp32
__device__ float g_p12[cBF * 1024];              // [p1 | p2]
__device__ float g_p12p[2 * cBF * 1024];         // split-K partials
__device__ float g_e2[cB * cF * cF];
__device__ __nv_bfloat16 g_whi[cH * cH];         // Ws_f hi
__device__ __nv_bfloat16 g_wlo[cH * cH];         // Ws_f lo
__device__ __nv_bfloat16 g_wrhi[1024 * cD];      // Wr remapped hi
__device__ __nv_bfloat16 g_wrlo[1024 * cD];      // Wr remapped lo
__device__ __nv_bfloat16 g_ahi[cMA * cH];        // obj hi
__device__ __nv_bfloat16 g_alo[cMA * cH];        // obj lo
__device__ __nv_bfloat16 g_fhi[cBF * cD];        // feat hi
__device__ __nv_bfloat16 g_flo[cBF * cD];        // feat lo

// ---------------- PTX helpers (all family-target-safe, sm_80+) ----------------
__device__ __forceinline__ uint32_t smem_u32(const void* p) {
    uint32_t a;
    asm("{ .reg .u64 t; cvta.to.shared.u64 t, %1; cvt.u32.u64 %0, t; }"
        : "=r"(a) : "l"(p));
    return a;
}
#define CPA(dst, src) \
    asm volatile("cp.async.cg.shared.global [%0], [%1], 16;" :: "r"(dst), "l"(src) : "memory")
#define CPC()  asm volatile("cp.async.commit_group;" ::: "memory")
#define CPW1() asm volatile("cp.async.wait_group 1;" ::: "memory")
#define CPW0() asm volatile("cp.async.wait_group 0;" ::: "memory")
#define LDSM4(r0, r1, r2, r3, addr) \
    asm volatile("ldmatrix.sync.aligned.m8n8.x4.shared.b16 {%0,%1,%2,%3}, [%4];" \
        : "=r"(r0), "=r"(r1), "=r"(r2), "=r"(r3) : "r"(addr))
#define MMA(c, a, b0, b1) \
    asm volatile("mma.sync.aligned.m16n8k16.row.col.f32.bf16.bf16.f32 " \
        "{%0,%1,%2,%3},{%4,%5,%6,%7},{%8,%9},{%0,%1,%2,%3};" \
        : "+f"((c)[0]), "+f"((c)[1]), "+f"((c)[2]), "+f"((c)[3]) \
        : "r"((a)[0]), "r"((a)[1]), "r"((a)[2]), "r"((a)[3]), "r"(b0), "r"(b1))

__device__ __forceinline__ void split1(float x, __nv_bfloat16& h, __nv_bfloat16& l) {
    h = __float2bfloat16_rn(x);
    l = __float2bfloat16_rn(x - __bfloat162float(h));
}

// ============================================================
// Pre-splits
// ============================================================
__global__ void k_wsplit(const float* __restrict__ w) {
    int i = blockIdx.x * 256 + threadIdx.x;          // 262144
    __nv_bfloat16 h, l; split1(w[i], h, l);
    g_whi[i] = h; g_wlo[i] = l;
}
__global__ void k_wrsplit(const float* __restrict__ w) {
    int n = blockIdx.x;                              // 1024
    for (int k = threadIdx.x; k < cD; k += 256) {
        float x = (n < 512) ? w[(size_t)n * 3072 + k]
                            : w[(size_t)(n - 512) * 3072 + 1536 + k];
        __nv_bfloat16 h, l; split1(x, h, l);
        g_wrhi[(size_t)n * cD + k] = h; g_wrlo[(size_t)n * cD + k] = l;
    }
}
__global__ void k_asplit(const float* __restrict__ a) {
    size_t i4 = (size_t)blockIdx.x * 256 + threadIdx.x;   // grid 23040 -> 5.9M float4
    float4 v = ((const float4*)a)[i4];
    __nv_bfloat16 h0, h1, h2, h3, l0, l1, l2, l3;
    split1(v.x, h0, l0); split1(v.y, h1, l1);
    split1(v.z, h2, l2); split1(v.w, h3, l3);
    ull hp = (ull)__bfloat16_as_ushort(h0) | ((ull)__bfloat16_as_ushort(h1) << 16)
           | ((ull)__bfloat16_as_ushort(h2) << 32) | ((ull)__bfloat16_as_ushort(h3) << 48);
    ull lp = (ull)__bfloat16_as_ushort(l0) | ((ull)__bfloat16_as_ushort(l1) << 16)
           | ((ull)__bfloat16_as_ushort(l2) << 32) | ((ull)__bfloat16_as_ushort(l3) << 48);
    ((ull*)g_ahi)[i4] = hp;
    ((ull*)g_alo)[i4] = lp;
}

// ============================================================
// Combined hidden-state biases: warp-per-row, hidden transposed in smem.
// grid 128 x 256thr; row r = bx*8+wid over [Wsh rows | Wrh rows].
// ============================================================
constexpr int SMEM_BIAS = (512 * 33 + 8 * 512) * 4;   // 83968 bytes

__global__ void __launch_bounds__(256, 1)
k_bias(const float* __restrict__ hidden,
       const float* __restrict__ Wsh, const float* __restrict__ bsh,
       const float* __restrict__ bsf,
       const float* __restrict__ Wrh, const float* __restrict__ brh,
       const float* __restrict__ brf) {
    extern __shared__ float sb[];
    float* sht = sb;                 // [512][33] transposed hidden (padded)
    float* ws  = sb + 512 * 33;      // [8][512] warp weight rows
    const int tid = threadIdx.x, wid = tid >> 5, lane = tid & 31;

    // hidden (32x512) -> sht[k*33+b]; consecutive tid -> consecutive k: stride-33 conflict-free
    for (int idx = tid; idx < cB * cH; idx += 256) {
        int b = idx >> 9, k = idx & 511;
        sht[k * 33 + b] = hidden[idx];
    }
    const int r = blockIdx.x * 8 + wid;      // 0..1023
    const float* wrow = (r < 512) ? (Wsh + (size_t)r * cH)
                                  : (Wrh + (size_t)(r - 512) * cH);
    for (int k = lane; k < cH; k += 32) ws[wid * cH + k] = wrow[k];
    __syncthreads();

    const float* wsr = ws + wid * cH;
    float acc = 0.f;
    #pragma unroll 8
    for (int k = 0; k < cH; ++k)
        acc += wsr[k] * sht[k * 33 + lane];   // broadcast x conflict-free

    if (r < 512) {
        g_cs[lane * cH + r] = acc + bsh[r] + bsf[r];
    } else {
        int r2 = r - 512;
        g_cr[lane * cH + r2] = acc + brh[r2] + brf[r2];
    }
}

// ============================================================
// Tensor-core GEMM via mma.sync bf16 (2-term split: hh + hl + lh)
// CTA tile 128x128, K-chunk 32, cp.async double buffer.
// 8 warps = 4(m) x 2(n); warp tile 32x64.
// MODE 1: grid (4, 360): n-tile = bx (fastest) so the 4 CTAs sharing an
//         A m-tile run adjacently -> A read from DRAM ~once (L2 reuse).
//         Epilogue tanh*was reduce -> g_epart[n-tile] slice.
// MODE 0: grid (10, 8, 2): split-K via bz -> g_p12p slice.
// ============================================================
constexpr int SMEM_TC = 81920;   // 2 stages x 4 matrices x 128 rows x 40 b16

template <int MODE>
__global__ void __launch_bounds__(256, 1) k_tc(const float* __restrict__ was) {
    constexpr int K   = MODE ? cH : cD;
    constexpr int NCH = MODE ? 16 : 24;
    const __nv_bfloat16* Ah = MODE ? g_ahi : g_fhi;
    const __nv_bfloat16* Al = MODE ? g_alo : g_flo;
    const __nv_bfloat16* Wh = MODE ? g_whi : g_wrhi;
    const __nv_bfloat16* Wl = MODE ? g_wlo : g_wrlo;

    const int m0  = (MODE ? blockIdx.y : blockIdx.x) * 128;
    const int nti = MODE ? blockIdx.x : blockIdx.y;
    const int n0  = nti * 128;
    const int kstart = MODE ? 0 : blockIdx.z * 768;

    extern __shared__ char sm[];
    const uint32_t S = smem_u32(sm);
    const int tid = threadIdx.x;
    const int wid = tid >> 5, l = tid & 31;
    const int wm = wid >> 1, wn = wid & 1;

    auto issue = [&](int c) {
        const int st = c & 1;
        const int kb = kstart + c * 32;
        const int row = tid >> 1, h = tid & 1;
        const uint32_t d0 = S + st * 40960 + row * 80 + h * 32;
        const __nv_bfloat16* s1 = Ah + (size_t)(m0 + row) * K + kb + 16 * h;
        CPA(d0, s1);           CPA(d0 + 16, s1 + 8);
        const __nv_bfloat16* s2 = Al + (size_t)(m0 + row) * K + kb + 16 * h;
        CPA(d0 + 10240, s2);   CPA(d0 + 10240 + 16, s2 + 8);
        const __nv_bfloat16* s3 = Wh + (size_t)(n0 + row) * K + kb + 16 * h;
        CPA(d0 + 20480, s3);   CPA(d0 + 20480 + 16, s3 + 8);
        const __nv_bfloat16* s4 = Wl + (size_t)(n0 + row) * K + kb + 16 * h;
        CPA(d0 + 30720, s4);   CPA(d0 + 30720 + 16, s4 + 8);
        CPC();
    };

    float acc[2][8][4];
    #pragma unroll
    for (int i = 0; i < 2; i++)
        #pragma unroll
        for (int j = 0; j < 8; j++)
            #pragma unroll
            for (int q = 0; q < 4; q++) acc[i][j][q] = 0.f;

    issue(0); issue(1);

    for (int c = 0; c < NCH; ++c) {
        if (c + 1 < NCH) { CPW1(); } else { CPW0(); }
        __syncthreads();
        const int st = c & 1;
        #pragma unroll
        for (int kb16 = 0; kb16 < 64; kb16 += 32) {     // byte offset of k16 step
            uint32_t aH[2][4], aL[2][4];
            const uint32_t abase = S + st * 40960 + (32 * wm + (l & 15)) * 80
                                 + kb16 + ((l >> 4) << 4);
            LDSM4(aH[0][0], aH[0][1], aH[0][2], aH[0][3], abase);
            LDSM4(aH[1][0], aH[1][1], aH[1][2], aH[1][3], abase + 1280);
            LDSM4(aL[0][0], aL[0][1], aL[0][2], aL[0][3], abase + 10240);
            LDSM4(aL[1][0], aL[1][1], aL[1][2], aL[1][3], abase + 10240 + 1280);
            uint32_t bH[8][2], bL[8][2];
            #pragma unroll
            for (int ntp = 0; ntp < 4; ++ntp) {
                const uint32_t bb = S + st * 40960 + 20480
                    + (64 * wn + 16 * ntp + (l & 7) + ((l >> 4) << 3)) * 80
                    + kb16 + (((l >> 3) & 1) << 4);
                LDSM4(bH[2 * ntp][0], bH[2 * ntp][1], bH[2 * ntp + 1][0], bH[2 * ntp + 1][1], bb);
                LDSM4(bL[2 * ntp][0], bL[2 * ntp][1], bL[2 * ntp + 1][0], bL[2 * ntp + 1][1], bb + 10240);
            }
            #pragma unroll
            for (int mt = 0; mt < 2; ++mt)
                #pragma unroll
                for (int nt = 0; nt < 8; ++nt) {
                    MMA(acc[mt][nt], aH[mt], bH[nt][0], bH[nt][1]);
                    MMA(acc[mt][nt], aH[mt], bL[nt][0], bL[nt][1]);
                    MMA(acc[mt][nt], aL[mt], bH[nt][0], bH[nt][1]);
                }
        }
        __syncthreads();
        if (c + 2 < NCH) issue(c + 2);
    }

    if constexpr (MODE == 1) {
        // fused tanh(y + cs)*was reduction over this CTA's 128 n-cols
        float* sred = (float*)sm;                     // [128][2]
        #pragma unroll
        for (int mt = 0; mt < 2; ++mt)
            #pragma unroll
            for (int rr = 0; rr < 2; ++rr) {
                const int row_l = 32 * wm + 16 * mt + (l >> 2) + 8 * rr;
                const int m = m0 + row_l;
                const int b = m / (cF * cNB);
                float p = 0.f;
                #pragma unroll
                for (int nt = 0; nt < 8; ++nt) {
                    const int n = n0 + 64 * wn + 8 * nt + 2 * (l & 3);
                    p += tanhf(acc[mt][nt][2 * rr]     + g_cs[b * cH + n])     * was[n];
                    p += tanhf(acc[mt][nt][2 * rr + 1] + g_cs[b * cH + n + 1]) * was[n + 1];
                }
                p += __shfl_xor_sync(0xffffffffu, p, 1);
                p += __shfl_xor_sync(0xffffffffu, p, 2);
                if ((l & 3) == 0) sred[row_l * 2 + wn] = p;
            }
        __syncthreads();
        if (tid < 128)
            g_epart[(size_t)nti * cMA + m0 + tid] = sred[tid * 2] + sred[tid * 2 + 1];
    } else {
        float* outp = g_p12p + (size_t)blockIdx.z * cBF * 1024;
        #pragma unroll
        for (int mt = 0; mt < 2; ++mt)
            #pragma unroll
            for (int rr = 0; rr < 2; ++rr) {
                const int m = m0 + 32 * wm + 16 * mt + (l >> 2) + 8 * rr;
                #pragma unroll
                for (int nt = 0; nt < 8; ++nt) {
                    const int n = n0 + 64 * wn + 8 * nt + 2 * (l & 3);
                    float2 v = make_float2(acc[mt][nt][2 * rr], acc[mt][nt][2 * rr + 1]);
                    *(float2*)&outp[(size_t)m * 1024 + n] = v;
                }
            }
    }
}

// split-K partial reduce: g_p12 = sum of 2 partials
__global__ void k_p12red() {
    const float4* s = (const float4*)g_p12p;
    float4* d = (float4*)g_p12;
    size_t i = (size_t)blockIdx.x * 256 + threadIdx.x;   // grid 1280
    float4 a = s[i], b = s[i + (size_t)cBF * 256];
    d[i] = make_float4(a.x + b.x, a.y + b.y, a.z + b.z, a.w + b.w);
}

// ============================================================
// softmax-36 + object attention + feat assembly (fp32 + bf16 split)
// ============================================================
__global__ void k_objatt(const float* __restrict__ obj, const float* __restrict__ i3d) {
    int bf = blockIdx.x;
    __shared__ float sa[cNB];
    int tid = threadIdx.x;
    if (tid < cNB) {
        int idx = bf * cNB + tid;
        sa[tid] = g_epart[idx] + g_epart[cMA + idx]
                + g_epart[2 * cMA + idx] + g_epart[3 * cMA + idx];
    }
    __syncthreads();
    float mx = -1e30f;
    #pragma unroll
    for (int j = 0; j < cNB; j++) mx = fmaxf(mx, sa[j]);
    float ssum = 0.f;
    #pragma unroll
    for (int j = 0; j < cNB; j++) ssum += expf(sa[j] - mx);
    float inv = 1.f / ssum;
    __syncthreads();
    if (tid < cNB) sa[tid] = expf(sa[tid] - mx) * inv;
    __syncthreads();

    const float* f0 = obj + (size_t)bf * cNB * 512;
    float* fo = g_feat + (size_t)bf * cD;
    for (int d = tid; d < 512; d += blockDim.x) {
        float a = 0.f;
        #pragma unroll
        for (int j = 0; j < cNB; j++) a += sa[j] * f0[j * 512 + d];
        fo[d] = a;
        __nv_bfloat16 h, l; split1(a, h, l);
        g_fhi[(size_t)bf * cD + d] = h; g_flo[(size_t)bf * cD + d] = l;
    }
    const float* i0 = i3d + (size_t)bf * 1024;
    for (int d = tid; d < 1024; d += blockDim.x) {
        float a = i0[d];
        fo[512 + d] = a;
        __nv_bfloat16 h, l; split1(a, h, l);
        g_fhi[(size_t)bf * cD + 512 + d] = h; g_flo[(size_t)bf * cD + 512 + d] = l;
    }
}

// ============================================================
// stage-2 logits
// ============================================================
__global__ void k_e2(const float* __restrict__ war) {
    int i = blockIdx.x, b = blockIdx.y;
    __shared__ float s2[cH];
    __shared__ float swar[cH];
    int tid = threadIdx.x;
    for (int h = tid; h < cH; h += blockDim.x) {
        s2[h]   = g_p12[(size_t)(b * cF + i) * 1024 + 512 + h] + g_cr[b * cH + h];
        swar[h] = war[h];
    }
    __syncthreads();
    int w = tid >> 5, lane = tid & 31;
    for (int j = w; j < cF; j += 8) {
        const float* p1 = g_p12 + (size_t)(b * cF + j) * 1024;
        float a = 0.f;
        #pragma unroll 4
        for (int h = lane; h < cH; h += 32)
            a += tanhf(p1[h] + s2[h]) * swar[h];
        #pragma unroll
        for (int o = 16; o; o >>= 1) a += __shfl_xor_sync(0xffffffffu, a, o);
        if (lane == 0) g_e2[b * 1600 + i * cF + j] = a;
    }
}

// ============================================================
// softmax-1600 + rel1/rel2 + output
// ============================================================
__global__ void k_rel(float* __restrict__ out) {
    int b = blockIdx.x;
    __shared__ float sa[1600];
    __shared__ float ssr[cF], ssc[cF];
    __shared__ float rbuf[256];
    int tid = threadIdx.x;

    float mx = -1e30f;
    for (int t = tid; t < 1600; t += 256) {
        float v = g_e2[b * 1600 + t];
        sa[t] = v;
        mx = fmaxf(mx, v);
    }
    rbuf[tid] = mx; __syncthreads();
    for (int s = 128; s; s >>= 1) {
        if (tid < s) rbuf[tid] = fmaxf(rbuf[tid], rbuf[tid + s]);
        __syncthreads();
    }
    mx = rbuf[0]; __syncthreads();

    float sum = 0.f;
    for (int t = tid; t < 1600; t += 256) {
        float v = expf(sa[t] - mx);
        sa[t] = v;
        sum += v;
    }
    rbuf[tid] = sum; __syncthreads();
    for (int s = 128; s; s >>= 1) {
        if (tid < s) rbuf[tid] += rbuf[tid + s];
        __syncthreads();
    }
    float inv = 1.f / rbuf[0];
    __syncthreads();

    if (tid < cF) {
        float rs = 0.f, cs2 = 0.f;
        for (int t = 0; t < cF; t++) {
            rs  += sa[tid * cF + t];
            cs2 += sa[t * cF + tid];
        }
        ssr[tid] = rs * inv;
        ssc[tid] = cs2 * inv;
    }
    __syncthreads();

    const float* fb = g_feat + (size_t)b * cF * cD;
    for (int d = tid; d < cD; d += 256) {
        float r1 = 0.f, r2 = 0.f;
        #pragma unroll 8
        for (int t = 0; t < cF; t++) {
            float f = fb[(size_t)t * cD + d];
            r1 += ssc[t] * f;
            r2 += ssr[t] * f;
        }
        out[b * 3072 + d]        = r1;
        out[b * 3072 + 1536 + d] = r2;
    }
}

// ============================================================
extern "C" void kernel_launch(void* const* d_in, const int* in_sizes, int n_in,
                              void* d_out, int out_size) {
    const float* i3d    = (const float*)d_in[0];
    const float* obj    = (const float*)d_in[1];
    const float* hidden = (const float*)d_in[2];
    const float* Wsf    = (const float*)d_in[3];
    const float* bsf    = (const float*)d_in[4];
    const float* Wsh    = (const float*)d_in[5];
    const float* bsh    = (const float*)d_in[6];
    const float* was    = (const float*)d_in[7];
    const float* Wrf    = (const float*)d_in[8];
    const float* brf    = (const float*)d_in[9];
    const float* Wrh    = (const float*)d_in[10];
    const float* brh    = (const float*)d_in[11];
    const float* war    = (const float*)d_in[12];
    float* out = (float*)d_out;

    cudaFuncSetAttribute(k_tc<1>, cudaFuncAttributeMaxDynamicSharedMemorySize, SMEM_TC);
    cudaFuncSetAttribute(k_tc<0>, cudaFuncAttributeMaxDynamicSharedMemorySize, SMEM_TC);
    cudaFuncSetAttribute(k_bias, cudaFuncAttributeMaxDynamicSharedMemorySize, SMEM_BIAS);

    k_wsplit<<<1024, 256>>>(Wsf);
    k_wrsplit<<<1024, 256>>>(Wrf);
    k_asplit<<<23040, 256>>>(obj);
    k_bias<<<128, 256, SMEM_BIAS>>>(hidden, Wsh, bsh, bsf, Wrh, brh, brf);
    k_tc<1><<<dim3(4, 360), 256, SMEM_TC>>>(was);
    k_objatt<<<cBF, 256>>>(obj, i3d);
    k_tc<0><<<dim3(10, 8, 2), 256, SMEM_TC>>>(nullptr);
    k_p12red<<<1280, 256>>>();
    k_e2<<<dim3(cF, cB), 256>>>(war);
    k_rel<<<cB, 256>>>(out);
}